// round 1
// baseline (speedup 1.0000x reference)
#include <cuda_runtime.h>

#define NN 50000
#define NE 800000
#define D 128
#define DOUT 64

// Scratch (allocation-free rule: __device__ globals)
__device__ float g_dinv[NN];            // degree, then rsqrt(degree) in place
__device__ float g_hw [NN * D];         // post-GEMM features
__device__ float g_acc[NN * D];         // aggregation accumulator
__device__ float g_h  [NN * D];         // layer output (relu(acc+b))

// ---------------- degree / dinv ----------------
__global__ void deg_init_kernel() {
    int i = blockIdx.x * blockDim.x + threadIdx.x;
    if (i < NN) g_dinv[i] = 1.0f;   // self loop
}

__global__ void deg_edges_kernel(const int* __restrict__ dst) {
    int e = blockIdx.x * blockDim.x + threadIdx.x;
    if (e < NE) atomicAdd(&g_dinv[dst[e]], 1.0f);
}

__global__ void dinv_kernel() {
    int i = blockIdx.x * blockDim.x + threadIdx.x;
    if (i < NN) g_dinv[i] = rsqrtf(g_dinv[i]);
}

// ---------------- tiled SGEMM: C = A(MxK) * B(KxN) [+ bias] ----------------
template<int BM, int BN, int BK, int TM, int TN, bool ADD_BIAS>
__global__ void sgemm_kernel(const float* __restrict__ A,
                             const float* __restrict__ B,
                             const float* __restrict__ bias,
                             float* __restrict__ C,
                             int M, int K, int N) {
    constexpr int THREADS = (BM / TM) * (BN / TN);
    __shared__ float As[BK][BM];
    __shared__ float Bs[BK][BN + 4];

    const int tx = threadIdx.x;
    const int trow = tx / (BN / TN);
    const int tcol = tx % (BN / TN);
    const int rowBase = blockIdx.y * BM;
    const int colBase = blockIdx.x * BN;

    float acc[TM][TN];
    #pragma unroll
    for (int i = 0; i < TM; i++)
        #pragma unroll
        for (int j = 0; j < TN; j++) acc[i][j] = 0.0f;

    for (int k0 = 0; k0 < K; k0 += BK) {
        // A tile (BM x BK) -> As[k][m]
        #pragma unroll
        for (int i = tx; i < BM * BK; i += THREADS) {
            int r = i / BK, c = i % BK;
            int gr = rowBase + r;
            As[c][r] = (gr < M) ? A[(size_t)gr * K + k0 + c] : 0.0f;
        }
        // B tile (BK x BN) -> Bs[k][n]
        #pragma unroll
        for (int i = tx; i < BK * BN; i += THREADS) {
            int r = i / BN, c = i % BN;
            Bs[r][c] = B[(size_t)(k0 + r) * N + colBase + c];
        }
        __syncthreads();

        #pragma unroll
        for (int k = 0; k < BK; k++) {
            float a[TM], b[TN];
            #pragma unroll
            for (int i = 0; i < TM; i++) a[i] = As[k][trow * TM + i];
            #pragma unroll
            for (int j = 0; j < TN; j++) b[j] = Bs[k][tcol * TN + j];
            #pragma unroll
            for (int i = 0; i < TM; i++)
                #pragma unroll
                for (int j = 0; j < TN; j++)
                    acc[i][j] += a[i] * b[j];
        }
        __syncthreads();
    }

    #pragma unroll
    for (int i = 0; i < TM; i++) {
        int gr = rowBase + trow * TM + i;
        if (gr >= M) continue;
        #pragma unroll
        for (int j = 0; j < TN; j++) {
            int gc = colBase + tcol * TN + j;
            float v = acc[i][j];
            if (ADD_BIAS) v += bias[gc];
            C[(size_t)gr * N + gc] = v;
        }
    }
}

// ---------------- self-loop init: acc[i,:] = dinv[i]^2 * hw[i,:] ----------------
__global__ void selfloop_kernel() {
    int idx = blockIdx.x * blockDim.x + threadIdx.x;  // over NN*32 float4
    if (idx >= NN * (D / 4)) return;
    int node = idx >> 5;
    float di = g_dinv[node];
    float s = di * di;
    float4 v = reinterpret_cast<const float4*>(g_hw)[idx];
    v.x *= s; v.y *= s; v.z *= s; v.w *= s;
    reinterpret_cast<float4*>(g_acc)[idx] = v;
}

// ---------------- edge scatter: one warp per edge ----------------
__global__ void scatter_kernel(const int* __restrict__ src,
                               const int* __restrict__ dst) {
    int warp = (blockIdx.x * blockDim.x + threadIdx.x) >> 5;
    int lane = threadIdx.x & 31;
    if (warp >= NE) return;
    int s = src[warp];
    int d = dst[warp];
    float norm = g_dinv[s] * g_dinv[d];
    float4 v = reinterpret_cast<const float4*>(g_hw + (size_t)s * D)[lane];
    v.x *= norm; v.y *= norm; v.z *= norm; v.w *= norm;
    float* p = g_acc + (size_t)d * D + lane * 4;
    asm volatile("red.global.add.v4.f32 [%0], {%1,%2,%3,%4};"
                 :: "l"(p), "f"(v.x), "f"(v.y), "f"(v.z), "f"(v.w)
                 : "memory");
}

// ---------------- h = relu(acc + bias) ----------------
__global__ void bias_relu_kernel(const float* __restrict__ bias) {
    int idx = blockIdx.x * blockDim.x + threadIdx.x;  // over NN*32 float4
    if (idx >= NN * (D / 4)) return;
    int col4 = idx & 31;
    float4 v = reinterpret_cast<const float4*>(g_acc)[idx];
    float4 b = reinterpret_cast<const float4*>(bias)[col4];
    v.x = fmaxf(v.x + b.x, 0.0f);
    v.y = fmaxf(v.y + b.y, 0.0f);
    v.z = fmaxf(v.z + b.z, 0.0f);
    v.w = fmaxf(v.w + b.w, 0.0f);
    reinterpret_cast<float4*>(g_h)[idx] = v;
}

// ---------------- launch ----------------
extern "C" void kernel_launch(void* const* d_in, const int* in_sizes, int n_in,
                              void* d_out, int out_size) {
    const float* x   = (const float*)d_in[0];
    const int* eidx  = (const int*)d_in[1];
    const float* W1  = (const float*)d_in[2];
    const float* b1  = (const float*)d_in[3];
    const float* W2  = (const float*)d_in[4];
    const float* b2  = (const float*)d_in[5];
    const float* W3  = (const float*)d_in[6];
    const float* b3  = (const float*)d_in[7];
    const float* Wfc = (const float*)d_in[8];
    const float* bfc = (const float*)d_in[9];
    float* out = (float*)d_out;

    const int* src = eidx;        // edge_index[0]
    const int* dst = eidx + NE;   // edge_index[1]

    float* hw;  cudaGetSymbolAddress((void**)&hw,  g_hw);
    float* h;   cudaGetSymbolAddress((void**)&h,   g_h);

    // degrees -> dinv
    deg_init_kernel<<<(NN + 255) / 256, 256>>>();
    deg_edges_kernel<<<(NE + 255) / 256, 256>>>(dst);
    dinv_kernel<<<(NN + 255) / 256, 256>>>();

    const int elem4 = NN * (D / 4);
    dim3 gemmGrid(1, (NN + 127) / 128);
    const int scatterBlocks = (NE * 32 + 255) / 256;

    const float* layerIn = x;
    const float* Ws[3] = {W1, W2, W3};
    const float* bs[3] = {b1, b2, b3};

    for (int l = 0; l < 3; l++) {
        sgemm_kernel<128, 128, 8, 8, 8, false><<<gemmGrid, 256>>>(
            layerIn, Ws[l], nullptr, hw, NN, D, D);
        selfloop_kernel<<<(elem4 + 255) / 256, 256>>>();
        scatter_kernel<<<scatterBlocks, 256>>>(src, dst);
        bias_relu_kernel<<<(elem4 + 255) / 256, 256>>>(bs[l]);
        layerIn = h;
    }

    // final FC: out = h @ Wfc + bfc  (N x 64)
    sgemm_kernel<128, 64, 8, 8, 4, true><<<dim3(1, (NN + 127) / 128), 256>>>(
        h, Wfc, bfc, out, NN, D, DOUT);
}

// round 2
// speedup vs baseline: 2.2193x; 2.2193x over previous
#include <cuda_runtime.h>

#define NN 50000
#define NE 800000
#define D 128
#define DOUT 64
#define SCAN_B 512
#define NBLK ((NN + SCAN_B - 1) / SCAN_B)   // 98

// ---- scratch (__device__ globals: allocation-free rule) ----
__device__ int   g_cnt[NN];
__device__ int   g_fill[NN];
__device__ int   g_rowptr[NN + 1];
__device__ float g_dinv[NN];
__device__ int   g_blksum[NBLK];
__device__ int   g_blkoff[NBLK];
__device__ int   g_ecol[NE];
__device__ float g_enorm[NE];
__device__ float g_a[NN * D];   // aggregated features
__device__ float g_h[NN * D];   // layer features

// ================= CSR build =================
__global__ void zero_cnt_kernel() {
    int i = blockIdx.x * blockDim.x + threadIdx.x;
    if (i < NN) g_cnt[i] = 0;
}

__global__ void count_kernel(const int* __restrict__ dst) {
    int e = blockIdx.x * blockDim.x + threadIdx.x;
    if (e < NE) atomicAdd(&g_cnt[dst[e]], 1);
}

// block-wise inclusive scan of g_cnt -> g_rowptr[i+1] (pre-offset), block sums,
// and dinv = rsqrt(cnt+1) fused in.
__global__ void scan1_kernel() {
    __shared__ int s[SCAN_B];
    int t = threadIdx.x;
    int i = blockIdx.x * SCAN_B + t;
    int v = (i < NN) ? g_cnt[i] : 0;
    if (i < NN) g_dinv[i] = rsqrtf((float)v + 1.0f);
    s[t] = v;
    __syncthreads();
    #pragma unroll
    for (int off = 1; off < SCAN_B; off <<= 1) {
        int x = (t >= off) ? s[t - off] : 0;
        __syncthreads();
        s[t] += x;
        __syncthreads();
    }
    if (i < NN) g_rowptr[i + 1] = s[t];
    if (t == SCAN_B - 1) g_blksum[blockIdx.x] = s[t];
}

__global__ void scan2_kernel() {
    __shared__ int s[128];
    int t = threadIdx.x;
    int v = (t < NBLK) ? g_blksum[t] : 0;
    s[t] = v;
    __syncthreads();
    #pragma unroll
    for (int off = 1; off < 128; off <<= 1) {
        int x = (t >= off) ? s[t - off] : 0;
        __syncthreads();
        s[t] += x;
        __syncthreads();
    }
    if (t < NBLK) g_blkoff[t] = s[t] - v;   // exclusive
}

__global__ void scan3_kernel() {
    int i = blockIdx.x * blockDim.x + threadIdx.x;
    if (i < NN) {
        g_rowptr[i + 1] += g_blkoff[i / SCAN_B];
        g_fill[i] = 0;
    }
    if (i == 0) g_rowptr[0] = 0;
}

__global__ void fill_kernel(const int* __restrict__ src,
                            const int* __restrict__ dst) {
    int e = blockIdx.x * blockDim.x + threadIdx.x;
    if (e >= NE) return;
    int s = src[e];
    int d = dst[e];
    int pos = g_rowptr[d] + atomicAdd(&g_fill[d], 1);
    g_ecol[pos] = s;
    g_enorm[pos] = g_dinv[s] * g_dinv[d];
}

// ================= aggregation: warp per node, CSR gather =================
__global__ void gather_kernel(const float* __restrict__ hin) {
    int node = (blockIdx.x * blockDim.x + threadIdx.x) >> 5;
    int lane = threadIdx.x & 31;
    if (node >= NN) return;

    float w = g_dinv[node];
    float sl = w * w;
    float4 own = __ldg((const float4*)(hin + (size_t)node * D) + lane);
    float4 acc;
    acc.x = sl * own.x; acc.y = sl * own.y; acc.z = sl * own.z; acc.w = sl * own.w;

    int e   = g_rowptr[node];
    int end = g_rowptr[node + 1];
    for (; e + 2 <= end; e += 2) {
        int   s0 = g_ecol[e],    s1 = g_ecol[e + 1];
        float w0 = g_enorm[e],   w1 = g_enorm[e + 1];
        float4 v0 = __ldg((const float4*)(hin + (size_t)s0 * D) + lane);
        float4 v1 = __ldg((const float4*)(hin + (size_t)s1 * D) + lane);
        acc.x = fmaf(w0, v0.x, acc.x); acc.y = fmaf(w0, v0.y, acc.y);
        acc.z = fmaf(w0, v0.z, acc.z); acc.w = fmaf(w0, v0.w, acc.w);
        acc.x = fmaf(w1, v1.x, acc.x); acc.y = fmaf(w1, v1.y, acc.y);
        acc.z = fmaf(w1, v1.z, acc.z); acc.w = fmaf(w1, v1.w, acc.w);
    }
    if (e < end) {
        int   s0 = g_ecol[e];
        float w0 = g_enorm[e];
        float4 v0 = __ldg((const float4*)(hin + (size_t)s0 * D) + lane);
        acc.x = fmaf(w0, v0.x, acc.x); acc.y = fmaf(w0, v0.y, acc.y);
        acc.z = fmaf(w0, v0.z, acc.z); acc.w = fmaf(w0, v0.w, acc.w);
    }
    ((float4*)(g_a + (size_t)node * D))[lane] = acc;
}

// ================= GEMM: C[M,BN] = A[M,128] * B[128,BN] (+bias, relu) =====
// Uses packed fp32x2 FMA (sm_103a) for 2x fp32 throughput.
template<int BN, int TN, bool RELU>
__global__ void __launch_bounds__(256, 2)
gemm_kernel(const float* __restrict__ A,
            const float* __restrict__ B,
            const float* __restrict__ bias,
            float* __restrict__ C, int M) {
    constexpr int BM = 128, BK = 8, TM = 8;
    constexpr int NT = BN / TN;                 // threads per row-dim = 16
    constexpr int BTHREADS = BK * BN / 4;       // threads loading B tile

    __shared__ float As[BK][BM + 4];
    __shared__ float Bs[BK][BN];

    const int tx = threadIdx.x;
    const int trow = tx / NT;
    const int tcol = tx % NT;
    const int rowBase = blockIdx.x * BM;

    // A tile load map: 1 float4 per thread (128x8 floats / 256 thr)
    const int aRow = tx >> 1;
    const int aCol = (tx & 1) * 4;
    // B tile load map
    const int bRow = tx / (BN / 4);
    const int bCol = (tx % (BN / 4)) * 4;

    float4 aReg = make_float4(0.f, 0.f, 0.f, 0.f);
    float4 bReg = make_float4(0.f, 0.f, 0.f, 0.f);
    {
        int gr = rowBase + aRow;
        if (gr < M) aReg = *(const float4*)(A + (size_t)gr * D + aCol);
        if (tx < BTHREADS) bReg = *(const float4*)(B + (size_t)bRow * BN + bCol);
    }

    unsigned long long acc[TM][TN / 2];
    #pragma unroll
    for (int i = 0; i < TM; i++)
        #pragma unroll
        for (int j = 0; j < TN / 2; j++) acc[i][j] = 0ull;

    #pragma unroll 1
    for (int kt = 0; kt < D / BK; kt++) {
        __syncthreads();
        As[aCol + 0][aRow] = aReg.x;
        As[aCol + 1][aRow] = aReg.y;
        As[aCol + 2][aRow] = aReg.z;
        As[aCol + 3][aRow] = aReg.w;
        if (tx < BTHREADS) *(float4*)&Bs[bRow][bCol] = bReg;
        __syncthreads();

        if (kt + 1 < D / BK) {
            int gr = rowBase + aRow;
            int c = (kt + 1) * BK + aCol;
            if (gr < M) aReg = *(const float4*)(A + (size_t)gr * D + c);
            if (tx < BTHREADS)
                bReg = *(const float4*)(B + (size_t)((kt + 1) * BK + bRow) * BN + bCol);
        }

        #pragma unroll
        for (int k = 0; k < BK; k++) {
            float4 a0 = *(const float4*)&As[k][trow * TM];
            float4 a1 = *(const float4*)&As[k][trow * TM + 4];
            float a[TM] = {a0.x, a0.y, a0.z, a0.w, a1.x, a1.y, a1.z, a1.w};

            unsigned long long bb[TN / 2];
            {
                union { float4 f; unsigned long long u[2]; } ub;
                ub.f = *(const float4*)&Bs[k][tcol * TN];
                bb[0] = ub.u[0];
                bb[1] = ub.u[1];
                if (TN == 8) {
                    ub.f = *(const float4*)&Bs[k][tcol * TN + 4];
                    bb[2] = ub.u[0];
                    bb[3] = ub.u[1];
                }
            }
            #pragma unroll
            for (int i = 0; i < TM; i++) {
                unsigned long long aa;
                asm("mov.b64 %0, {%1, %1};" : "=l"(aa) : "f"(a[i]));
                #pragma unroll
                for (int j = 0; j < TN / 2; j++) {
                    asm("fma.rn.f32x2 %0, %1, %2, %3;"
                        : "=l"(acc[i][j]) : "l"(aa), "l"(bb[j]), "l"(acc[i][j]));
                }
            }
        }
    }

    // epilogue: + bias, optional relu
    #pragma unroll
    for (int i = 0; i < TM; i++) {
        int gr = rowBase + trow * TM + i;
        if (gr >= M) continue;
        #pragma unroll
        for (int j = 0; j < TN / 2; j++) {
            float lo, hi;
            asm("mov.b64 {%0, %1}, %2;" : "=f"(lo), "=f"(hi) : "l"(acc[i][j]));
            int gc = tcol * TN + j * 2;
            lo += bias[gc];
            hi += bias[gc + 1];
            if (RELU) { lo = fmaxf(lo, 0.0f); hi = fmaxf(hi, 0.0f); }
            float2 v = make_float2(lo, hi);
            *(float2*)(C + (size_t)gr * BN + gc) = v;
        }
    }
}

// ================= launch =================
extern "C" void kernel_launch(void* const* d_in, const int* in_sizes, int n_in,
                              void* d_out, int out_size) {
    const float* x   = (const float*)d_in[0];
    const int* eidx  = (const int*)d_in[1];
    const float* W1  = (const float*)d_in[2];
    const float* b1  = (const float*)d_in[3];
    const float* W2  = (const float*)d_in[4];
    const float* b2  = (const float*)d_in[5];
    const float* W3  = (const float*)d_in[6];
    const float* b3  = (const float*)d_in[7];
    const float* Wfc = (const float*)d_in[8];
    const float* bfc = (const float*)d_in[9];
    float* out = (float*)d_out;

    const int* src = eidx;        // edge_index[0]
    const int* dst = eidx + NE;   // edge_index[1]

    float* a; cudaGetSymbolAddress((void**)&a, g_a);
    float* h; cudaGetSymbolAddress((void**)&h, g_h);

    // CSR build (per launch; graph-capturable, allocation-free)
    zero_cnt_kernel<<<(NN + 255) / 256, 256>>>();
    count_kernel<<<(NE + 255) / 256, 256>>>(dst);
    scan1_kernel<<<NBLK, SCAN_B>>>();
    scan2_kernel<<<1, 128>>>();
    scan3_kernel<<<(NN + 255) / 256, 256>>>();
    fill_kernel<<<(NE + 255) / 256, 256>>>(src, dst);

    const int gatherBlocks = (NN * 32 + 255) / 256;
    const int gemmBlocks = (NN + 127) / 128;

    const float* layerIn = x;
    const float* Ws[3] = {W1, W2, W3};
    const float* bs[3] = {b1, b2, b3};

    for (int l = 0; l < 3; l++) {
        gather_kernel<<<gatherBlocks, 256>>>(layerIn);           // g_a = Ahat @ layerIn
        gemm_kernel<128, 8, true><<<gemmBlocks, 256>>>(a, Ws[l], bs[l], h, NN);
        layerIn = h;
    }

    // final FC: out = h @ Wfc + bfc
    gemm_kernel<64, 4, false><<<gemmBlocks, 256>>>(h, Wfc, bfc, out, NN);
}

// round 4
// speedup vs baseline: 2.8199x; 1.2706x over previous
#include <cuda_runtime.h>
#include <cstdint>

#define NN 50000
#define NE 800000
#define D 128
#define DOUT 64
#define SCAN_B 512
#define NBLK ((NN + SCAN_B - 1) / SCAN_B)   // 98

// ---- scratch (__device__ globals: allocation-free rule) ----
__device__ int   g_cnt[NN];
__device__ int   g_fill[NN];
__device__ int   g_rowptr[NN + 1];
__device__ float g_dinv[NN];
__device__ int   g_blksum[NBLK];
__device__ int   g_blkoff[NBLK];
__device__ int   g_ecol[NE];
__device__ float g_t[NN * D];         // GEMM output (dinv-scaled)
__device__ float g_h[NN * D];         // layer features
__device__ float g_wt_hi[3][D * D];   // W^T split: hi tf32
__device__ float g_wt_lo[3][D * D];   // lo tf32
__device__ float g_wfc_hi[DOUT * D];
__device__ float g_wfc_lo[DOUT * D];

// ================= helpers =================
__device__ __forceinline__ float tf32rn(float x) {
    uint32_t r;
    asm("cvt.rna.tf32.f32 %0, %1;" : "=r"(r) : "f"(x));
    return __uint_as_float(r);
}
__device__ __forceinline__ void split_tf32(float x, uint32_t& hi, uint32_t& lo) {
    asm("cvt.rna.tf32.f32 %0, %1;" : "=r"(hi) : "f"(x));
    float r = x - __uint_as_float(hi);
    asm("cvt.rna.tf32.f32 %0, %1;" : "=r"(lo) : "f"(r));
}
__device__ __forceinline__ void mma_tf32(float* c, const uint32_t* a, const uint32_t* b) {
    asm volatile(
        "mma.sync.aligned.m16n8k8.row.col.f32.tf32.tf32.f32 "
        "{%0,%1,%2,%3}, {%4,%5,%6,%7}, {%8,%9}, {%0,%1,%2,%3};"
        : "+f"(c[0]), "+f"(c[1]), "+f"(c[2]), "+f"(c[3])
        : "r"(a[0]), "r"(a[1]), "r"(a[2]), "r"(a[3]), "r"(b[0]), "r"(b[1]));
}

// ================= CSR build =================
__global__ void zero_cnt_kernel() {
    int i = blockIdx.x * blockDim.x + threadIdx.x;
    if (i < NN) g_cnt[i] = 0;
}
__global__ void count_kernel(const int* __restrict__ dst) {
    int e = blockIdx.x * blockDim.x + threadIdx.x;
    if (e < NE) atomicAdd(&g_cnt[dst[e]], 1);
}
__global__ void scan1_kernel() {
    __shared__ int s[SCAN_B];
    int t = threadIdx.x;
    int i = blockIdx.x * SCAN_B + t;
    int v = (i < NN) ? g_cnt[i] : 0;
    if (i < NN) g_dinv[i] = rsqrtf((float)v + 1.0f);
    s[t] = v;
    __syncthreads();
    #pragma unroll
    for (int off = 1; off < SCAN_B; off <<= 1) {
        int x = (t >= off) ? s[t - off] : 0;
        __syncthreads();
        s[t] += x;
        __syncthreads();
    }
    if (i < NN) g_rowptr[i + 1] = s[t];
    if (t == SCAN_B - 1) g_blksum[blockIdx.x] = s[t];
}
__global__ void scan2_kernel() {
    __shared__ int s[128];
    int t = threadIdx.x;
    int v = (t < NBLK) ? g_blksum[t] : 0;
    s[t] = v;
    __syncthreads();
    #pragma unroll
    for (int off = 1; off < 128; off <<= 1) {
        int x = (t >= off) ? s[t - off] : 0;
        __syncthreads();
        s[t] += x;
        __syncthreads();
    }
    if (t < NBLK) g_blkoff[t] = s[t] - v;
}
__global__ void scan3_kernel() {
    int i = blockIdx.x * blockDim.x + threadIdx.x;
    if (i < NN) {
        g_rowptr[i + 1] += g_blkoff[i / SCAN_B];
        g_fill[i] = 0;
    }
    if (i == 0) g_rowptr[0] = 0;
}
__global__ void fill_kernel(const int* __restrict__ src,
                            const int* __restrict__ dst) {
    int e = blockIdx.x * blockDim.x + threadIdx.x;
    if (e >= NE) return;
    int d = dst[e];
    int pos = g_rowptr[d] + atomicAdd(&g_fill[d], 1);
    g_ecol[pos] = src[e];
}

// ===== weight transpose + tf32 hi/lo split: W[K,Ncols] -> hi/lo[Ncols,K] =====
__global__ void wsplit_kernel(const float* __restrict__ W, float* __restrict__ hi,
                              float* __restrict__ lo, int ncols) {
    int idx = blockIdx.x * blockDim.x + threadIdx.x;
    if (idx >= ncols * D) return;
    int n = idx / D, k = idx % D;
    float w = W[k * ncols + n];
    float h_ = tf32rn(w);
    hi[idx] = h_;
    lo[idx] = tf32rn(w - h_);
}

// ===== mma.sync tf32 GEMM: C[M,BN] = A[M,128] @ (Bhi+Blo)^T, 3-term split =====
// EPI 0: C[r,:] = acc * g_dinv[r]      EPI 1: C[r,:] = acc + bias[:]
template<int BN, int EPI>
__global__ void __launch_bounds__(256, 1)
mma_gemm_kernel(const float* __restrict__ A,
                const float* __restrict__ Bhi,
                const float* __restrict__ Blo,
                const float* __restrict__ bias,
                float* __restrict__ C, int M) {
    constexpr int TN_W = BN / 2;   // warp n-extent (64 or 32)
    constexpr int NT = TN_W / 8;   // n8 tiles per warp (8 or 4)
    constexpr int LDS = 132;
    extern __shared__ float s[];
    float* As = s;                     // [128][132] fp32
    float* Bh = s + 128 * LDS;         // [BN][132]  tf32 hi (as fp32 bits)
    float* Bl = Bh + BN * LDS;         // [BN][132]  tf32 lo

    const int tid = threadIdx.x;
    const int lane = tid & 31, warp = tid >> 5;
    const int warpM = warp & 3, warpN = warp >> 2;
    const int rowBlk = blockIdx.x * 128;
    const int g = lane >> 2, tig = lane & 3;

    // ---- load A tile (fp32, coalesced float4) ----
    #pragma unroll
    for (int i = 0; i < 16; i++) {
        int idx = i * 256 + tid;
        int r = idx >> 5, c4 = idx & 31;
        float4 v = make_float4(0.f, 0.f, 0.f, 0.f);
        if (rowBlk + r < M) v = ((const float4*)A)[(size_t)(rowBlk + r) * 32 + c4];
        *(float4*)(As + r * LDS + c4 * 4) = v;
    }
    // ---- load B hi/lo tiles ([BN][128] row-major = W^T) ----
    #pragma unroll
    for (int i = 0; i < BN / 8; i++) {
        int idx = i * 256 + tid;
        int r = idx >> 5, c4 = idx & 31;
        *(float4*)(Bh + r * LDS + c4 * 4) = ((const float4*)Bhi)[(size_t)r * 32 + c4];
        *(float4*)(Bl + r * LDS + c4 * 4) = ((const float4*)Blo)[(size_t)r * 32 + c4];
    }
    __syncthreads();

    float acc[2][NT][4];
    #pragma unroll
    for (int mt = 0; mt < 2; mt++)
        #pragma unroll
        for (int nt = 0; nt < NT; nt++)
            #pragma unroll
            for (int q = 0; q < 4; q++) acc[mt][nt][q] = 0.f;

    const int aBase = warpM * 32;
    const int nBase = warpN * TN_W;

    #pragma unroll 4
    for (int ks = 0; ks < 16; ks++) {
        const int k0 = ks * 8;
        // A fragments, hi/lo split in registers
        uint32_t ahi[2][4], alo[2][4];
        #pragma unroll
        for (int mt = 0; mt < 2; mt++) {
            int r0 = aBase + mt * 16 + g;
            float a0 = As[r0 * LDS + k0 + tig];
            float a1 = As[(r0 + 8) * LDS + k0 + tig];
            float a2 = As[r0 * LDS + k0 + tig + 4];
            float a3 = As[(r0 + 8) * LDS + k0 + tig + 4];
            split_tf32(a0, ahi[mt][0], alo[mt][0]);
            split_tf32(a1, ahi[mt][1], alo[mt][1]);
            split_tf32(a2, ahi[mt][2], alo[mt][2]);
            split_tf32(a3, ahi[mt][3], alo[mt][3]);
        }
        // B fragments (pre-split)
        uint32_t bhi[NT][2], blo[NT][2];
        #pragma unroll
        for (int nt = 0; nt < NT; nt++) {
            int n = nBase + nt * 8 + g;
            bhi[nt][0] = __float_as_uint(Bh[n * LDS + k0 + tig]);
            bhi[nt][1] = __float_as_uint(Bh[n * LDS + k0 + tig + 4]);
            blo[nt][0] = __float_as_uint(Bl[n * LDS + k0 + tig]);
            blo[nt][1] = __float_as_uint(Bl[n * LDS + k0 + tig + 4]);
        }
        // 3-term compensated MMA (term-major for ILP across acc tiles)
        #pragma unroll
        for (int mt = 0; mt < 2; mt++)
            #pragma unroll
            for (int nt = 0; nt < NT; nt++)
                mma_tf32(acc[mt][nt], ahi[mt], bhi[nt]);
        #pragma unroll
        for (int mt = 0; mt < 2; mt++)
            #pragma unroll
            for (int nt = 0; nt < NT; nt++)
                mma_tf32(acc[mt][nt], alo[mt], bhi[nt]);
        #pragma unroll
        for (int mt = 0; mt < 2; mt++)
            #pragma unroll
            for (int nt = 0; nt < NT; nt++)
                mma_tf32(acc[mt][nt], ahi[mt], blo[nt]);
    }

    // ---- epilogue ----
    #pragma unroll
    for (int mt = 0; mt < 2; mt++) {
        int r0 = rowBlk + aBase + mt * 16 + g;
        int r1 = r0 + 8;
        float s0 = 1.f, s1 = 1.f;
        if (EPI == 0) {
            if (r0 < M) s0 = g_dinv[r0];
            if (r1 < M) s1 = g_dinv[r1];
        }
        #pragma unroll
        for (int nt = 0; nt < NT; nt++) {
            int cn = nBase + nt * 8 + 2 * tig;
            float2 v0 = make_float2(acc[mt][nt][0], acc[mt][nt][1]);
            float2 v1 = make_float2(acc[mt][nt][2], acc[mt][nt][3]);
            if (EPI == 0) {
                v0.x *= s0; v0.y *= s0; v1.x *= s1; v1.y *= s1;
            } else {
                float b0 = bias[cn], b1 = bias[cn + 1];
                v0.x += b0; v0.y += b1; v1.x += b0; v1.y += b1;
            }
            if (r0 < M) *(float2*)(C + (size_t)r0 * BN + cn) = v0;
            if (r1 < M) *(float2*)(C + (size_t)r1 * BN + cn) = v1;
        }
    }
}

// ================= aggregation: warp per node, pure-sum CSR gather =================
__global__ void gather_kernel(const float* __restrict__ tin,
                              const float* __restrict__ bias,
                              float* __restrict__ hout) {
    int node = (blockIdx.x * blockDim.x + threadIdx.x) >> 5;
    int lane = threadIdx.x & 31;
    if (node >= NN) return;
    const float4* t4 = (const float4*)tin;

    float4 acc = __ldg(t4 + (size_t)node * 32 + lane);  // self term
    int e = g_rowptr[node], end = g_rowptr[node + 1];
    for (; e + 4 <= end; e += 4) {
        int s0 = g_ecol[e], s1 = g_ecol[e + 1], s2 = g_ecol[e + 2], s3 = g_ecol[e + 3];
        float4 v0 = __ldg(t4 + (size_t)s0 * 32 + lane);
        float4 v1 = __ldg(t4 + (size_t)s1 * 32 + lane);
        float4 v2 = __ldg(t4 + (size_t)s2 * 32 + lane);
        float4 v3 = __ldg(t4 + (size_t)s3 * 32 + lane);
        v0.x += v1.x; v0.y += v1.y; v0.z += v1.z; v0.w += v1.w;
        v2.x += v3.x; v2.y += v3.y; v2.z += v3.z; v2.w += v3.w;
        acc.x += v0.x + v2.x; acc.y += v0.y + v2.y;
        acc.z += v0.z + v2.z; acc.w += v0.w + v2.w;
    }
    for (; e < end; e++) {
        float4 v = __ldg(t4 + (size_t)g_ecol[e] * 32 + lane);
        acc.x += v.x; acc.y += v.y; acc.z += v.z; acc.w += v.w;
    }
    float dd = g_dinv[node];
    float4 b = ((const float4*)bias)[lane];
    acc.x = fmaxf(fmaf(dd, acc.x, b.x), 0.0f);
    acc.y = fmaxf(fmaf(dd, acc.y, b.y), 0.0f);
    acc.z = fmaxf(fmaf(dd, acc.z, b.z), 0.0f);
    acc.w = fmaxf(fmaf(dd, acc.w, b.w), 0.0f);
    ((float4*)hout)[(size_t)node * 32 + lane] = acc;
}

// ================= launch =================
extern "C" void kernel_launch(void* const* d_in, const int* in_sizes, int n_in,
                              void* d_out, int out_size) {
    const float* x   = (const float*)d_in[0];
    const int* eidx  = (const int*)d_in[1];
    const float* W1  = (const float*)d_in[2];
    const float* b1  = (const float*)d_in[3];
    const float* W2  = (const float*)d_in[4];
    const float* b2  = (const float*)d_in[5];
    const float* W3  = (const float*)d_in[6];
    const float* b3  = (const float*)d_in[7];
    const float* Wfc = (const float*)d_in[8];
    const float* bfc = (const float*)d_in[9];
    float* out = (float*)d_out;

    const int* src = eidx;
    const int* dst = eidx + NE;

    float* t; cudaGetSymbolAddress((void**)&t, g_t);
    float* h; cudaGetSymbolAddress((void**)&h, g_h);
    float* whi; cudaGetSymbolAddress((void**)&whi, g_wt_hi);
    float* wlo; cudaGetSymbolAddress((void**)&wlo, g_wt_lo);
    float* fhi; cudaGetSymbolAddress((void**)&fhi, g_wfc_hi);
    float* flo; cudaGetSymbolAddress((void**)&flo, g_wfc_lo);

    // CSR build
    zero_cnt_kernel<<<(NN + 255) / 256, 256>>>();
    count_kernel<<<(NE + 255) / 256, 256>>>(dst);
    scan1_kernel<<<NBLK, SCAN_B>>>();
    scan2_kernel<<<1, 128>>>();
    scan3_kernel<<<(NN + 255) / 256, 256>>>();
    fill_kernel<<<(NE + 255) / 256, 256>>>(src, dst);

    // weight transpose + tf32 split
    const float* Ws[3] = {W1, W2, W3};
    for (int l = 0; l < 3; l++)
        wsplit_kernel<<<(D * D + 255) / 256, 256>>>(Ws[l], whi + l * D * D,
                                                    wlo + l * D * D, D);
    wsplit_kernel<<<(DOUT * D + 255) / 256, 256>>>(Wfc, fhi, flo, DOUT);

    const int SMEM128 = (128 + 2 * 128) * 132 * 4;  // 202752
    const int SMEM64  = (128 + 2 * 64) * 132 * 4;   // 135168
    cudaFuncSetAttribute(mma_gemm_kernel<128, 0>,
                         cudaFuncAttributeMaxDynamicSharedMemorySize, SMEM128);
    cudaFuncSetAttribute(mma_gemm_kernel<64, 1>,
                         cudaFuncAttributeMaxDynamicSharedMemorySize, SMEM64);

    const int gemmBlocks = (NN + 127) / 128;
    const int gatherBlocks = (NN * 32 + 255) / 256;
    const float* bs[3] = {b1, b2, b3};

    const float* layerIn = x;
    for (int l = 0; l < 3; l++) {
        mma_gemm_kernel<128, 0><<<gemmBlocks, 256, SMEM128>>>(
            layerIn, whi + l * D * D, wlo + l * D * D, nullptr, t, NN);
        gather_kernel<<<gatherBlocks, 256>>>(t, bs[l], h);
        layerIn = h;
    }
    mma_gemm_kernel<64, 1><<<gemmBlocks, 256, SMEM64>>>(h, fhi, flo, bfc, out, NN);
}

// round 5
// speedup vs baseline: 3.1495x; 1.1169x over previous
#include <cuda_runtime.h>
#include <cuda_fp16.h>
#include <cstdint>

#define NN 50000
#define NE 800000
#define D 128
#define DOUT 64
#define SCAN_B 512
#define NBLK ((NN + SCAN_B - 1) / SCAN_B)   // 98

// ---- scratch (__device__ globals: allocation-free rule) ----
__device__ int    g_cnt[NN];
__device__ int    g_fill[NN];
__device__ int    g_rowptr[NN + 1];
__device__ float  g_dinv[NN];
__device__ int    g_blksum[NBLK];
__device__ int    g_ecol[NE];
__device__ __half g_t[NN * D];         // GEMM output (dinv-scaled, fp16 messages)
__device__ float  g_h[NN * D];         // layer features (fp32)
__device__ float  g_wt_hi[3][D * D];   // W^T split: hi tf32
__device__ float  g_wt_lo[3][D * D];   // lo tf32
__device__ float  g_wfc_hi[DOUT * D];
__device__ float  g_wfc_lo[DOUT * D];

// ================= helpers =================
__device__ __forceinline__ float tf32rn(float x) {
    uint32_t r;
    asm("cvt.rna.tf32.f32 %0, %1;" : "=r"(r) : "f"(x));
    return __uint_as_float(r);
}
__device__ __forceinline__ void split_tf32(float x, uint32_t& hi, uint32_t& lo) {
    asm("cvt.rna.tf32.f32 %0, %1;" : "=r"(hi) : "f"(x));
    float r = x - __uint_as_float(hi);
    asm("cvt.rna.tf32.f32 %0, %1;" : "=r"(lo) : "f"(r));
}
__device__ __forceinline__ void mma_tf32(float* c, const uint32_t* a, const uint32_t* b) {
    asm volatile(
        "mma.sync.aligned.m16n8k8.row.col.f32.tf32.tf32.f32 "
        "{%0,%1,%2,%3}, {%4,%5,%6,%7}, {%8,%9}, {%0,%1,%2,%3};"
        : "+f"(c[0]), "+f"(c[1]), "+f"(c[2]), "+f"(c[3])
        : "r"(a[0]), "r"(a[1]), "r"(a[2]), "r"(a[3]), "r"(b[0]), "r"(b[1]));
}

// ================= CSR build =================
__global__ void count_kernel(const int* __restrict__ dst) {
    int e = blockIdx.x * blockDim.x + threadIdx.x;
    if (e < NE) atomicAdd(&g_cnt[dst[e]], 1);
}
__global__ void scan1_kernel() {
    __shared__ int s[SCAN_B];
    int t = threadIdx.x;
    int i = blockIdx.x * SCAN_B + t;
    int v = (i < NN) ? g_cnt[i] : 0;
    if (i < NN) g_dinv[i] = rsqrtf((float)v + 1.0f);
    s[t] = v;
    __syncthreads();
    #pragma unroll
    for (int off = 1; off < SCAN_B; off <<= 1) {
        int x = (t >= off) ? s[t - off] : 0;
        __syncthreads();
        s[t] += x;
        __syncthreads();
    }
    if (i < NN) g_rowptr[i + 1] = s[t];
    if (t == SCAN_B - 1) g_blksum[blockIdx.x] = s[t];
}
// fused: every block re-scans the 98 block sums, then applies its offsets
__global__ void scan23_kernel() {
    __shared__ int s[128];
    int t = threadIdx.x;   // 256 threads
    if (t < 128) s[t] = (t < NBLK) ? g_blksum[t] : 0;
    __syncthreads();
    #pragma unroll
    for (int off = 1; off < 128; off <<= 1) {
        int x = (t >= off && t < 128) ? s[t - off] : 0;
        __syncthreads();
        if (t < 128) s[t] += x;
        __syncthreads();
    }
    int i = blockIdx.x * 256 + t;
    if (i < NN) {
        int blk = i / SCAN_B;
        int off = (blk > 0) ? s[blk - 1] : 0;
        g_rowptr[i + 1] += off;
        g_fill[i] = 0;
    }
    if (i == 0) g_rowptr[0] = 0;
}
__global__ void fill_kernel(const int* __restrict__ src,
                            const int* __restrict__ dst) {
    int e = blockIdx.x * blockDim.x + threadIdx.x;
    if (e >= NE) return;
    int d = dst[e];
    int pos = g_rowptr[d] + atomicAdd(&g_fill[d], 1);
    g_ecol[pos] = src[e];
}

// ===== all-weight transpose + tf32 hi/lo split (one kernel) =====
__global__ void wsplit_all_kernel(const float* __restrict__ W1,
                                  const float* __restrict__ W2,
                                  const float* __restrict__ W3,
                                  const float* __restrict__ Wfc) {
    int idx = blockIdx.x * blockDim.x + threadIdx.x;
    const int SQ = D * D;
    const float* W;
    float *hi, *lo;
    int ncols, local;
    if (idx < SQ)            { W = W1;  hi = g_wt_hi[0]; lo = g_wt_lo[0]; ncols = D;    local = idx; }
    else if (idx < 2 * SQ)   { W = W2;  hi = g_wt_hi[1]; lo = g_wt_lo[1]; ncols = D;    local = idx - SQ; }
    else if (idx < 3 * SQ)   { W = W3;  hi = g_wt_hi[2]; lo = g_wt_lo[2]; ncols = D;    local = idx - 2 * SQ; }
    else if (idx < 3 * SQ + DOUT * D)
                             { W = Wfc; hi = g_wfc_hi;   lo = g_wfc_lo;   ncols = DOUT; local = idx - 3 * SQ; }
    else return;
    int n = local / D, k = local % D;
    float w = W[k * ncols + n];
    float h_ = tf32rn(w);
    hi[local] = h_;
    lo[local] = tf32rn(w - h_);
}

// ===== mma.sync tf32 GEMM: C[M,BN] = A[M,128] @ (Bhi+Blo)^T, 3-term split =====
// EPI 0: half2 C[r,:] = acc * g_dinv[r]      EPI 1: float C[r,:] = acc + bias[:]
template<int BN, int EPI>
__global__ void __launch_bounds__(256, 1)
mma_gemm_kernel(const float* __restrict__ A,
                const float* __restrict__ Bhi,
                const float* __restrict__ Blo,
                const float* __restrict__ bias,
                void* __restrict__ Cout, int M) {
    constexpr int TN_W = BN / 2;
    constexpr int NT = TN_W / 8;
    constexpr int LDS = 132;
    extern __shared__ float s[];
    float* As = s;
    float* Bh = s + 128 * LDS;
    float* Bl = Bh + BN * LDS;

    const int tid = threadIdx.x;
    const int lane = tid & 31, warp = tid >> 5;
    const int warpM = warp & 3, warpN = warp >> 2;
    const int rowBlk = blockIdx.x * 128;
    const int g = lane >> 2, tig = lane & 3;

    #pragma unroll
    for (int i = 0; i < 16; i++) {
        int idx = i * 256 + tid;
        int r = idx >> 5, c4 = idx & 31;
        float4 v = make_float4(0.f, 0.f, 0.f, 0.f);
        if (rowBlk + r < M) v = ((const float4*)A)[(size_t)(rowBlk + r) * 32 + c4];
        *(float4*)(As + r * LDS + c4 * 4) = v;
    }
    #pragma unroll
    for (int i = 0; i < BN / 8; i++) {
        int idx = i * 256 + tid;
        int r = idx >> 5, c4 = idx & 31;
        *(float4*)(Bh + r * LDS + c4 * 4) = ((const float4*)Bhi)[(size_t)r * 32 + c4];
        *(float4*)(Bl + r * LDS + c4 * 4) = ((const float4*)Blo)[(size_t)r * 32 + c4];
    }
    __syncthreads();

    float acc[2][NT][4];
    #pragma unroll
    for (int mt = 0; mt < 2; mt++)
        #pragma unroll
        for (int nt = 0; nt < NT; nt++)
            #pragma unroll
            for (int q = 0; q < 4; q++) acc[mt][nt][q] = 0.f;

    const int aBase = warpM * 32;
    const int nBase = warpN * TN_W;

    #pragma unroll 4
    for (int ks = 0; ks < 16; ks++) {
        const int k0 = ks * 8;
        uint32_t ahi[2][4], alo[2][4];
        #pragma unroll
        for (int mt = 0; mt < 2; mt++) {
            int r0 = aBase + mt * 16 + g;
            float a0 = As[r0 * LDS + k0 + tig];
            float a1 = As[(r0 + 8) * LDS + k0 + tig];
            float a2 = As[r0 * LDS + k0 + tig + 4];
            float a3 = As[(r0 + 8) * LDS + k0 + tig + 4];
            split_tf32(a0, ahi[mt][0], alo[mt][0]);
            split_tf32(a1, ahi[mt][1], alo[mt][1]);
            split_tf32(a2, ahi[mt][2], alo[mt][2]);
            split_tf32(a3, ahi[mt][3], alo[mt][3]);
        }
        uint32_t bhi[NT][2], blo[NT][2];
        #pragma unroll
        for (int nt = 0; nt < NT; nt++) {
            int n = nBase + nt * 8 + g;
            bhi[nt][0] = __float_as_uint(Bh[n * LDS + k0 + tig]);
            bhi[nt][1] = __float_as_uint(Bh[n * LDS + k0 + tig + 4]);
            blo[nt][0] = __float_as_uint(Bl[n * LDS + k0 + tig]);
            blo[nt][1] = __float_as_uint(Bl[n * LDS + k0 + tig + 4]);
        }
        #pragma unroll
        for (int mt = 0; mt < 2; mt++)
            #pragma unroll
            for (int nt = 0; nt < NT; nt++)
                mma_tf32(acc[mt][nt], ahi[mt], bhi[nt]);
        #pragma unroll
        for (int mt = 0; mt < 2; mt++)
            #pragma unroll
            for (int nt = 0; nt < NT; nt++)
                mma_tf32(acc[mt][nt], alo[mt], bhi[nt]);
        #pragma unroll
        for (int mt = 0; mt < 2; mt++)
            #pragma unroll
            for (int nt = 0; nt < NT; nt++)
                mma_tf32(acc[mt][nt], ahi[mt], blo[nt]);
    }

    #pragma unroll
    for (int mt = 0; mt < 2; mt++) {
        int r0 = rowBlk + aBase + mt * 16 + g;
        int r1 = r0 + 8;
        float s0 = 1.f, s1 = 1.f;
        if (EPI == 0) {
            if (r0 < M) s0 = g_dinv[r0];
            if (r1 < M) s1 = g_dinv[r1];
        }
        #pragma unroll
        for (int nt = 0; nt < NT; nt++) {
            int cn = nBase + nt * 8 + 2 * tig;
            float2 v0 = make_float2(acc[mt][nt][0], acc[mt][nt][1]);
            float2 v1 = make_float2(acc[mt][nt][2], acc[mt][nt][3]);
            if (EPI == 0) {
                v0.x *= s0; v0.y *= s0; v1.x *= s1; v1.y *= s1;
                __half* Ch = (__half*)Cout;
                if (r0 < M) *(__half2*)(Ch + (size_t)r0 * BN + cn) = __float22half2_rn(v0);
                if (r1 < M) *(__half2*)(Ch + (size_t)r1 * BN + cn) = __float22half2_rn(v1);
            } else {
                float b0 = bias[cn], b1 = bias[cn + 1];
                v0.x += b0; v0.y += b1; v1.x += b0; v1.y += b1;
                float* Cf = (float*)Cout;
                if (r0 < M) *(float2*)(Cf + (size_t)r0 * BN + cn) = v0;
                if (r1 < M) *(float2*)(Cf + (size_t)r1 * BN + cn) = v1;
            }
        }
    }
}

// ========= aggregation: warp per node, fp16 messages, fp32 accumulate =========
__device__ __forceinline__ float4 ldrow_h(const uint2* __restrict__ t2, int row, int lane) {
    uint2 u = __ldg(t2 + (size_t)row * 32 + lane);
    float2 fa = __half22float2(*(__half2*)&u.x);
    float2 fb = __half22float2(*(__half2*)&u.y);
    return make_float4(fa.x, fa.y, fb.x, fb.y);
}

__global__ void gather_kernel(const __half* __restrict__ tin,
                              const float* __restrict__ bias,
                              float* __restrict__ hout) {
    int node = (blockIdx.x * blockDim.x + threadIdx.x) >> 5;
    int lane = threadIdx.x & 31;
    if (node >= NN) return;
    const uint2* t2 = (const uint2*)tin;

    float4 acc = ldrow_h(t2, node, lane);   // self term (dinv-scaled)
    int e = g_rowptr[node], end = g_rowptr[node + 1];
    for (; e + 4 <= end; e += 4) {
        int s0 = g_ecol[e], s1 = g_ecol[e + 1], s2 = g_ecol[e + 2], s3 = g_ecol[e + 3];
        float4 v0 = ldrow_h(t2, s0, lane);
        float4 v1 = ldrow_h(t2, s1, lane);
        float4 v2 = ldrow_h(t2, s2, lane);
        float4 v3 = ldrow_h(t2, s3, lane);
        v0.x += v1.x; v0.y += v1.y; v0.z += v1.z; v0.w += v1.w;
        v2.x += v3.x; v2.y += v3.y; v2.z += v3.z; v2.w += v3.w;
        acc.x += v0.x + v2.x; acc.y += v0.y + v2.y;
        acc.z += v0.z + v2.z; acc.w += v0.w + v2.w;
    }
    for (; e < end; e++) {
        float4 v = ldrow_h(t2, g_ecol[e], lane);
        acc.x += v.x; acc.y += v.y; acc.z += v.z; acc.w += v.w;
    }
    float dd = g_dinv[node];
    float4 b = ((const float4*)bias)[lane];
    acc.x = fmaxf(fmaf(dd, acc.x, b.x), 0.0f);
    acc.y = fmaxf(fmaf(dd, acc.y, b.y), 0.0f);
    acc.z = fmaxf(fmaf(dd, acc.z, b.z), 0.0f);
    acc.w = fmaxf(fmaf(dd, acc.w, b.w), 0.0f);
    ((float4*)hout)[(size_t)node * 32 + lane] = acc;
}

// ================= launch =================
extern "C" void kernel_launch(void* const* d_in, const int* in_sizes, int n_in,
                              void* d_out, int out_size) {
    const float* x   = (const float*)d_in[0];
    const int* eidx  = (const int*)d_in[1];
    const float* W1  = (const float*)d_in[2];
    const float* b1  = (const float*)d_in[3];
    const float* W2  = (const float*)d_in[4];
    const float* b2  = (const float*)d_in[5];
    const float* W3  = (const float*)d_in[6];
    const float* b3  = (const float*)d_in[7];
    const float* Wfc = (const float*)d_in[8];
    const float* bfc = (const float*)d_in[9];
    float* out = (float*)d_out;

    const int* src = eidx;
    const int* dst = eidx + NE;

    __half* t; cudaGetSymbolAddress((void**)&t, g_t);
    float* h;  cudaGetSymbolAddress((void**)&h, g_h);
    int* cnt;  cudaGetSymbolAddress((void**)&cnt, g_cnt);
    float* whi; cudaGetSymbolAddress((void**)&whi, g_wt_hi);
    float* wlo; cudaGetSymbolAddress((void**)&wlo, g_wt_lo);
    float* fhi; cudaGetSymbolAddress((void**)&fhi, g_wfc_hi);
    float* flo; cudaGetSymbolAddress((void**)&flo, g_wfc_lo);

    // CSR build
    cudaMemsetAsync(cnt, 0, NN * sizeof(int));
    count_kernel<<<(NE + 255) / 256, 256>>>(dst);
    scan1_kernel<<<NBLK, SCAN_B>>>();
    scan23_kernel<<<(NN + 255) / 256, 256>>>();
    fill_kernel<<<(NE + 255) / 256, 256>>>(src, dst);

    // all weight splits in one kernel
    const int WTOT = 3 * D * D + DOUT * D;
    wsplit_all_kernel<<<(WTOT + 255) / 256, 256>>>(W1, W2, W3, Wfc);

    const int SMEM128 = (128 + 2 * 128) * 132 * 4;  // 202752
    const int SMEM64  = (128 + 2 * 64) * 132 * 4;   // 135168
    cudaFuncSetAttribute(mma_gemm_kernel<128, 0>,
                         cudaFuncAttributeMaxDynamicSharedMemorySize, SMEM128);
    cudaFuncSetAttribute(mma_gemm_kernel<64, 1>,
                         cudaFuncAttributeMaxDynamicSharedMemorySize, SMEM64);

    const int gemmBlocks = (NN + 127) / 128;
    const int gatherBlocks = (NN * 32 + 255) / 256;
    const float* bs[3] = {b1, b2, b3};

    const float* layerIn = x;
    for (int l = 0; l < 3; l++) {
        mma_gemm_kernel<128, 0><<<gemmBlocks, 256, SMEM128>>>(
            layerIn, whi + l * D * D, wlo + l * D * D, nullptr, t, NN);
        gather_kernel<<<gatherBlocks, 256>>>(t, bs[l], h);
        layerIn = h;
    }
    mma_gemm_kernel<64, 1><<<gemmBlocks, 256, SMEM64>>>(h, fhi, flo, bfc, out, NN);
}